// round 13
// baseline (speedup 1.0000x reference)
#include <cuda_runtime.h>
#include <cuda_bf16.h>
#include <math.h>
#include <stdint.h>

#define HEADS 16
#define HD    64
#define SEQ   2048
#define BATCH 2
#define DIMM  1024
#define TDIM  3072
#define BT    (BATCH*SEQ)

// Scratch (no cudaMalloc allowed)
__device__ float g_qkv[(size_t)BT * TDIM];          // tf32-rounded qkv
__device__ float g_att[(size_t)BT * DIMM];          // attention output (fp32)
__device__ __nv_bfloat16 g_xh[(size_t)BT * DIMM];
__device__ __nv_bfloat16 g_xl[(size_t)BT * DIMM];
__device__ __nv_bfloat16 g_w1h[(size_t)TDIM * DIMM];
__device__ __nv_bfloat16 g_w1l[(size_t)TDIM * DIMM];
__device__ __nv_bfloat16 g_w2h[(size_t)DIMM * DIMM];
__device__ __nv_bfloat16 g_w2l[(size_t)DIMM * DIMM];
__device__ __nv_bfloat16 g_ah[(size_t)BT * DIMM];
__device__ __nv_bfloat16 g_al[(size_t)BT * DIMM];

__device__ __forceinline__ float to_tf32(float x) {
    uint32_t u;
    asm("cvt.rna.tf32.f32 %0, %1;" : "=r"(u) : "f"(x));
    return __uint_as_float(u);
}
__device__ __forceinline__ float ex2(float x) {
    float y;
    asm("ex2.approx.ftz.f32 %0, %1;" : "=f"(y) : "f"(x));
    return y;
}
__device__ __forceinline__ void mma_tf32(float* c, const uint32_t* a, const uint32_t* b) {
    asm volatile(
        "mma.sync.aligned.m16n8k8.row.col.f32.tf32.tf32.f32 "
        "{%0,%1,%2,%3}, {%4,%5,%6,%7}, {%8,%9}, {%0,%1,%2,%3};\n"
        : "+f"(c[0]), "+f"(c[1]), "+f"(c[2]), "+f"(c[3])
        : "r"(a[0]), "r"(a[1]), "r"(a[2]), "r"(a[3]), "r"(b[0]), "r"(b[1]));
}
__device__ __forceinline__ void mma_bf16(float* c, const uint32_t* a, const uint32_t* b) {
    asm volatile(
        "mma.sync.aligned.m16n8k16.row.col.f32.bf16.bf16.f32 "
        "{%0,%1,%2,%3}, {%4,%5,%6,%7}, {%8,%9}, {%0,%1,%2,%3};\n"
        : "+f"(c[0]), "+f"(c[1]), "+f"(c[2]), "+f"(c[3])
        : "r"(a[0]), "r"(a[1]), "r"(a[2]), "r"(a[3]), "r"(b[0]), "r"(b[1]));
}
__device__ __forceinline__ void cp16(uint32_t s, const void* g) {
    asm volatile("cp.async.cg.shared.global [%0], [%1], 16;" :: "r"(s), "l"(g));
}
#define CP_COMMIT() asm volatile("cp.async.commit_group;")
#define CP_WAIT1()  asm volatile("cp.async.wait_group 1;")

// ---------------------------------------------------------------------------
// Prepass: fp32 -> (hi, lo) bf16 split.  x = hi + lo with ~2^-17 residual.
// ---------------------------------------------------------------------------
__global__ void split_kernel(const float4* __restrict__ src,
                             __nv_bfloat162* __restrict__ hi,
                             __nv_bfloat162* __restrict__ lo, int n4)
{
    int i = blockIdx.x * 256 + threadIdx.x;
    if (i >= n4) return;
    float4 v = src[i];
    __nv_bfloat16 h0 = __float2bfloat16(v.x), h1 = __float2bfloat16(v.y);
    __nv_bfloat16 h2 = __float2bfloat16(v.z), h3 = __float2bfloat16(v.w);
    __nv_bfloat16 l0 = __float2bfloat16(v.x - __bfloat162float(h0));
    __nv_bfloat16 l1 = __float2bfloat16(v.y - __bfloat162float(h1));
    __nv_bfloat16 l2 = __float2bfloat16(v.z - __bfloat162float(h2));
    __nv_bfloat16 l3 = __float2bfloat16(v.w - __bfloat162float(h3));
    hi[2 * i]     = __halves2bfloat162(h0, h1);
    hi[2 * i + 1] = __halves2bfloat162(h2, h3);
    lo[2 * i]     = __halves2bfloat162(l0, l1);
    lo[2 * i + 1] = __halves2bfloat162(l2, l3);
}

// ---------------------------------------------------------------------------
// bf16x3 GEMM: C = Ah@Bh^T + Al@Bh^T + Ah@Bl^T + bias  (~fp32 accuracy)
// mma.sync m16n8k16 bf16. BM=BN=128, BK=64 bf16, 256 threads, warp tile 32x64.
// 2-stage cp.async; smem rows 72 bf16 (144B) -> conflict-free frag LDS (4g+t).
// smem bytes: A st0 @0, A st1 @18432, W st0 @36864, W st1 @55296; total 73728.
// ---------------------------------------------------------------------------
template<bool ROUND_OUT>
__global__ __launch_bounds__(256, 2) void bf_gemm(
    const __nv_bfloat16* __restrict__ Ah, const __nv_bfloat16* __restrict__ Al,
    const __nv_bfloat16* __restrict__ Bh, const __nv_bfloat16* __restrict__ Bl,
    const float* __restrict__ bias, float* __restrict__ C, int N, int K)
{
    extern __shared__ __nv_bfloat16 smb[];
    const uint32_t sbase = (uint32_t)__cvta_generic_to_shared(smb);
    const uint32_t* Awords = (const uint32_t*)smb;

    const int tid  = threadIdx.x;
    const int warp = tid >> 5;
    const int lane = tid & 31;
    const int g    = lane >> 2;
    const int t    = lane & 3;
    const int m0 = blockIdx.y * 128;
    const int n0 = blockIdx.x * 128;
    const int wm = (warp >> 1) * 32;
    const int wn = (warp & 1) * 64;

    const int nkc = K / 64;
    const int tot = 3 * nkc;
    const __nv_bfloat16* APh[3] = {Ah, Al, Ah};
    const __nv_bfloat16* BPh[3] = {Bh, Bh, Bl};

    const uint32_t aoff[2] = {0u, 18432u};
    const uint32_t woff[2] = {36864u, 55296u};

    auto load_chunk = [&](int it, int s) {
        const int ph = it / nkc;
        const int kk = (it - ph * nkc) * 64;
        const __nv_bfloat16* Asrc = APh[ph];
        const __nv_bfloat16* Bsrc = BPh[ph];
#pragma unroll
        for (int j = 0; j < 4; j++) {
            const int li = tid + j * 256;          // 0..1023
            const int r  = li >> 3;                // row 0..127
            const int c  = (li & 7) * 8;           // bf16 col 0..56
            cp16(sbase + aoff[s] + (uint32_t)(r * 144 + c * 2), Asrc + (size_t)(m0 + r) * K + kk + c);
            cp16(sbase + woff[s] + (uint32_t)(r * 144 + c * 2), Bsrc + (size_t)(n0 + r) * K + kk + c);
        }
        CP_COMMIT();
    };

    float acc[2][8][4];
#pragma unroll
    for (int mi = 0; mi < 2; mi++)
#pragma unroll
        for (int ni = 0; ni < 8; ni++)
#pragma unroll
            for (int r = 0; r < 4; r++) acc[mi][ni][r] = 0.f;

    load_chunk(0, 0);
    load_chunk(1, 1);

    for (int it = 0; it < tot; it++) {
        const int s = it & 1;
        CP_WAIT1();
        __syncthreads();

        const int aw = (int)(aoff[s] >> 2);
        const int ww = (int)(woff[s] >> 2);
#pragma unroll
        for (int ks = 0; ks < 4; ks++) {
            uint32_t af[2][4], bf[8][2];
#pragma unroll
            for (int mi = 0; mi < 2; mi++) {
                const int base = aw + (wm + mi * 16 + g) * 36 + ks * 8 + t;
                af[mi][0] = Awords[base];
                af[mi][1] = Awords[base + 8 * 36];
                af[mi][2] = Awords[base + 4];
                af[mi][3] = Awords[base + 8 * 36 + 4];
            }
#pragma unroll
            for (int ni = 0; ni < 8; ni++) {
                const int base = ww + (wn + ni * 8 + g) * 36 + ks * 8 + t;
                bf[ni][0] = Awords[base];
                bf[ni][1] = Awords[base + 4];
            }
#pragma unroll
            for (int mi = 0; mi < 2; mi++)
#pragma unroll
                for (int ni = 0; ni < 8; ni++)
                    mma_bf16(acc[mi][ni], af[mi], bf[ni]);
        }
        __syncthreads();

        if (it + 2 < tot) load_chunk(it + 2, s);
        else CP_COMMIT();
    }

#pragma unroll
    for (int mi = 0; mi < 2; mi++) {
#pragma unroll
        for (int ni = 0; ni < 8; ni++) {
            const int n = n0 + wn + ni * 8 + 2 * t;
            const float b0 = bias[n], b1 = bias[n + 1];
            const int mA = m0 + wm + mi * 16 + g;
            float2 v0, v1;
            if (ROUND_OUT) {
                v0.x = to_tf32(acc[mi][ni][0] + b0); v0.y = to_tf32(acc[mi][ni][1] + b1);
                v1.x = to_tf32(acc[mi][ni][2] + b0); v1.y = to_tf32(acc[mi][ni][3] + b1);
            } else {
                v0.x = acc[mi][ni][0] + b0; v0.y = acc[mi][ni][1] + b1;
                v1.x = acc[mi][ni][2] + b0; v1.y = acc[mi][ni][3] + b1;
            }
            *(float2*)&C[(size_t)mA * N + n] = v0;
            *(float2*)&C[(size_t)(mA + 8) * N + n] = v1;
        }
    }
}

// ---------------------------------------------------------------------------
// Flash attention, tf32 mma, cp.async double-buffered K/V.
// PV permute via per-warp-private smem P tile (no shuffles); P fed to
// tf32 mma as raw fp32 (HW truncation). Q frags in regs; 1 CTA/SM.
// smem floats: stage0 [0,8704), stage1 [8704,17408), P/Qstage [17408,26112).
// ---------------------------------------------------------------------------
__global__ __launch_bounds__(256, 1) void attn_mma(const int* __restrict__ causal_p,
                                                   float* __restrict__ out)
{
    extern __shared__ float sm[];
    float* Ps = sm + 2 * 8704;

    const int qtile = (int)(gridDim.x - 1 - blockIdx.x);   // heavy tiles first
    const int bh    = blockIdx.y;
    const int b     = bh >> 4;
    const int h     = bh & 15;
    const int tid   = threadIdx.x;
    const int w     = tid >> 5;
    const int lane  = tid & 31;
    const int g     = lane >> 2;
    const int t     = lane & 3;
    const int causal = *causal_p;

    const float sscale = 0.125f * 1.4426950408889634f;
    const float slope2 = (float)(exp2(-0.5 * (double)(h + 1)) * 1.4426950408889634);

    const float* qkv = g_qkv;
    const int q0 = qtile * 128;
    const int rg  = q0 + w * 16 + g;
    const int rg8 = rg + 8;

    const uint32_t smu = (uint32_t)__cvta_generic_to_shared(sm);

    // KV tile 0 -> stage 0
#pragma unroll
    for (int itr = 0; itr < 4; itr++) {
        const int i = itr * 256 + tid;
        const int row = i >> 4;
        const int c4  = (i & 15) * 4;
        const float* gk = qkv + (size_t)(b * SEQ + row) * TDIM + h * HD + DIMM + c4;
        const uint32_t dk = smu + (uint32_t)(row * 68 + c4) * 4;
        cp16(dk, gk);
        cp16(dk + 4352 * 4, gk + DIMM);
    }
    CP_COMMIT();

    // Q -> P region (staging), fragment to registers
    for (int itr = 0; itr < 8; itr++) {
        const int i = itr * 256 + tid;
        const int row = i >> 4;
        const int c4  = (i & 15) * 4;
        *(float4*)&Ps[row * 68 + c4] =
            *(const float4*)&qkv[(size_t)(b * SEQ + q0 + row) * TDIM + h * HD + c4];
    }
    __syncthreads();

    uint32_t qa[8][4];
#pragma unroll
    for (int k = 0; k < 8; k++) {
        qa[k][0] = __float_as_uint(Ps[(w * 16 + g    ) * 68 + k * 8 + t    ]);
        qa[k][1] = __float_as_uint(Ps[(w * 16 + g + 8) * 68 + k * 8 + t    ]);
        qa[k][2] = __float_as_uint(Ps[(w * 16 + g    ) * 68 + k * 8 + t + 4]);
        qa[k][3] = __float_as_uint(Ps[(w * 16 + g + 8) * 68 + k * 8 + t + 4]);
    }
    __syncthreads();

    const int ntiles = causal ? (2 * qtile + 2) : (SEQ / 64);

    // KV tile 1 -> stage 1
    if (ntiles > 1) {
#pragma unroll
        for (int itr = 0; itr < 4; itr++) {
            const int i = itr * 256 + tid;
            const int row = i >> 4;
            const int c4  = (i & 15) * 4;
            const float* gk = qkv + (size_t)(b * SEQ + 64 + row) * TDIM + h * HD + DIMM + c4;
            const uint32_t dk = smu + (uint32_t)(8704 + row * 68 + c4) * 4;
            cp16(dk, gk);
            cp16(dk + 4352 * 4, gk + DIMM);
        }
    }
    CP_COMMIT();

    float o[8][4];
#pragma unroll
    for (int ni = 0; ni < 8; ni++)
#pragma unroll
        for (int r = 0; r < 4; r++) o[ni][r] = 0.f;
    float m0 = -1e30f, m1 = -1e30f, l0 = 0.f, l1 = 0.f;

    float* Pw0 = Ps + (w * 16 + g) * 68;
    float* Pw1 = Pw0 + 8 * 68;

    for (int kt = 0; kt < ntiles; kt++) {
        CP_WAIT1();
        __syncthreads();

        const float* Ks = sm + (kt & 1) * 8704;
        const float* Vs = Ks + 4352;

        const bool active = !(causal && kt * 64 > q0 + w * 16 + 15);
        if (active) {
            // ---- S = Q K^T ----
            float sc[8][4];
#pragma unroll
            for (int ni = 0; ni < 8; ni++)
#pragma unroll
                for (int r = 0; r < 4; r++) sc[ni][r] = 0.f;

#pragma unroll
            for (int k = 0; k < 8; k++) {
                uint32_t kb[8][2];
#pragma unroll
                for (int ni = 0; ni < 8; ni++) {
                    kb[ni][0] = __float_as_uint(Ks[(ni * 8 + g) * 68 + k * 8 + t    ]);
                    kb[ni][1] = __float_as_uint(Ks[(ni * 8 + g) * 68 + k * 8 + t + 4]);
                }
#pragma unroll
                for (int ni = 0; ni < 8; ni++)
                    mma_tf32(sc[ni], qa[k], kb[ni]);
            }

            // ---- Online softmax (log2 domain, ALiBi analytic) ----
            float mx0 = -1e30f, mx1 = -1e30f;
#pragma unroll
            for (int ni = 0; ni < 8; ni++) {
#pragma unroll
                for (int e = 0; e < 2; e++) {
                    const int col = kt * 64 + ni * 8 + 2 * t + e;
                    float v0 = fmaf(sc[ni][e],     sscale, slope2 * (float)(col - rg));
                    float v1 = fmaf(sc[ni][2 + e], sscale, slope2 * (float)(col - rg8));
                    if (causal && col > rg)  v0 = -1e30f;
                    if (causal && col > rg8) v1 = -1e30f;
                    sc[ni][e]     = v0;
                    sc[ni][2 + e] = v1;
                    mx0 = fmaxf(mx0, v0);
                    mx1 = fmaxf(mx1, v1);
                }
            }
            mx0 = fmaxf(mx0, __shfl_xor_sync(0xffffffffu, mx0, 1));
            mx0 = fmaxf(mx0, __shfl_xor_sync(0xffffffffu, mx0, 2));
            mx1 = fmaxf(mx1, __shfl_xor_sync(0xffffffffu, mx1, 1));
            mx1 = fmaxf(mx1, __shfl_xor_sync(0xffffffffu, mx1, 2));

            const float mn0 = fmaxf(m0, mx0);
            const float mn1 = fmaxf(m1, mx1);
            const float rs0 = ex2(m0 - mn0);
            const float rs1 = ex2(m1 - mn1);

            float sum0 = 0.f, sum1 = 0.f;
#pragma unroll
            for (int ni = 0; ni < 8; ni++) {
                float p00 = ex2(sc[ni][0] - mn0);
                float p01 = ex2(sc[ni][1] - mn0);
                float p10 = ex2(sc[ni][2] - mn1);
                float p11 = ex2(sc[ni][3] - mn1);
                sum0 += p00 + p01;
                sum1 += p10 + p11;
                float2 w0v; w0v.x = p00; w0v.y = p01;
                float2 w1v; w1v.x = p10; w1v.y = p11;
                *(float2*)&Pw0[ni * 8 + 2 * t] = w0v;   // row rg,  cols 2t,2t+1
                *(float2*)&Pw1[ni * 8 + 2 * t] = w1v;   // row rg8
            }
            sum0 += __shfl_xor_sync(0xffffffffu, sum0, 1);
            sum0 += __shfl_xor_sync(0xffffffffu, sum0, 2);
            sum1 += __shfl_xor_sync(0xffffffffu, sum1, 1);
            sum1 += __shfl_xor_sync(0xffffffffu, sum1, 2);

            l0 = l0 * rs0 + sum0;
            l1 = l1 * rs1 + sum1;
            m0 = mn0; m1 = mn1;
#pragma unroll
            for (int ni = 0; ni < 8; ni++) {
                o[ni][0] *= rs0; o[ni][1] *= rs0;
                o[ni][2] *= rs1; o[ni][3] *= rs1;
            }
            __syncwarp();   // P tile (warp-private rows) visible to whole warp

            // ---- O += P V : a-frags straight from smem P tile ----
#pragma unroll
            for (int kc = 0; kc < 8; kc++) {
                uint32_t pa[4];
                pa[0] = __float_as_uint(Pw0[kc * 8 + t    ]);
                pa[1] = __float_as_uint(Pw1[kc * 8 + t    ]);
                pa[2] = __float_as_uint(Pw0[kc * 8 + t + 4]);
                pa[3] = __float_as_uint(Pw1[kc * 8 + t + 4]);

                uint32_t vb[8][2];
#pragma unroll
                for (int ni = 0; ni < 8; ni++) {
                    vb[ni][0] = __float_as_uint(Vs[(kc * 8 + t    ) * 68 + ni * 8 + g]);
                    vb[ni][1] = __float_as_uint(Vs[(kc * 8 + t + 4) * 68 + ni * 8 + g]);
                }
#pragma unroll
                for (int ni = 0; ni < 8; ni++)
                    mma_tf32(o[ni], pa, vb[ni]);
            }
            __syncwarp();   // P reads done before next tile overwrites
        }
        __syncthreads();

        // Prefetch tile kt+2 into stage (kt&1)
        if (kt + 2 < ntiles) {
#pragma unroll
            for (int itr = 0; itr < 4; itr++) {
                const int i = itr * 256 + tid;
                const int row = i >> 4;
                const int c4  = (i & 15) * 4;
                const float* gk = qkv + (size_t)(b * SEQ + (kt + 2) * 64 + row) * TDIM + h * HD + DIMM + c4;
                const uint32_t dk = smu + (uint32_t)((kt & 1) * 8704 + row * 68 + c4) * 4;
                cp16(dk, gk);
                cp16(dk + 4352 * 4, gk + DIMM);
            }
        }
        CP_COMMIT();
    }

    // ---- Epilogue (plain fp32; GEMM3 splits it to bf16 anyway) ----
    const float inv0 = 1.f / l0;
    const float inv1 = 1.f / l1;
    const size_t row0 = (size_t)(b * SEQ + rg ) * DIMM + h * HD;
    const size_t row1 = (size_t)(b * SEQ + rg8) * DIMM + h * HD;
#pragma unroll
    for (int ni = 0; ni < 8; ni++) {
        const int n = ni * 8 + 2 * t;
        float2 v0; v0.x = o[ni][0] * inv0; v0.y = o[ni][1] * inv0;
        *(float2*)&out[row0 + n] = v0;
        float2 v1; v1.x = o[ni][2] * inv1; v1.y = o[ni][3] * inv1;
        *(float2*)&out[row1 + n] = v1;
    }
}

extern "C" void kernel_launch(void* const* d_in, const int* in_sizes, int n_in,
                              void* d_out, int out_size)
{
    const float* x      = (const float*)d_in[0];
    const int*   causal = (const int*)d_in[1];
    // d_in[2] = alibi_bias: unused (computed analytically in-kernel)
    const float* Wqkv   = (const float*)d_in[3];
    const float* bqkv   = (const float*)d_in[4];
    const float* Wout   = (const float*)d_in[5];
    const float* bout   = (const float*)d_in[6];
    float* out = (float*)d_out;

    float *qkv, *att;
    __nv_bfloat16 *xh, *xl, *w1h, *w1l, *w2h, *w2l, *ah, *al;
    cudaGetSymbolAddress((void**)&qkv, g_qkv);
    cudaGetSymbolAddress((void**)&att, g_att);
    cudaGetSymbolAddress((void**)&xh, g_xh);   cudaGetSymbolAddress((void**)&xl, g_xl);
    cudaGetSymbolAddress((void**)&w1h, g_w1h); cudaGetSymbolAddress((void**)&w1l, g_w1l);
    cudaGetSymbolAddress((void**)&w2h, g_w2h); cudaGetSymbolAddress((void**)&w2l, g_w2l);
    cudaGetSymbolAddress((void**)&ah, g_ah);   cudaGetSymbolAddress((void**)&al, g_al);

    const int gemm_smem = 73728;              // bf_gemm: 2 stages A+W
    const int attn_smem = 3 * 8704 * 4;       // 104448 B: 2 KV stages + P tile
    static bool attr_set = false;
    if (!attr_set) {
        cudaFuncSetAttribute(bf_gemm<true>,  cudaFuncAttributeMaxDynamicSharedMemorySize, gemm_smem);
        cudaFuncSetAttribute(bf_gemm<false>, cudaFuncAttributeMaxDynamicSharedMemorySize, gemm_smem);
        cudaFuncSetAttribute(attn_mma, cudaFuncAttributeMaxDynamicSharedMemorySize, attn_smem);
        attr_set = true;
    }

    // Splits (hi/lo bf16)
    split_kernel<<<BT * DIMM / 4 / 256, 256>>>((const float4*)x, (__nv_bfloat162*)xh, (__nv_bfloat162*)xl, BT * DIMM / 4);
    split_kernel<<<TDIM * DIMM / 4 / 256, 256>>>((const float4*)Wqkv, (__nv_bfloat162*)w1h, (__nv_bfloat162*)w1l, TDIM * DIMM / 4);
    split_kernel<<<DIMM * DIMM / 4 / 256, 256>>>((const float4*)Wout, (__nv_bfloat162*)w2h, (__nv_bfloat162*)w2l, DIMM * DIMM / 4);

    // QKV projection (bf16x3, tf32-rounded output for attention)
    dim3 g1(TDIM / 128, BT / 128);
    bf_gemm<true><<<g1, 256, gemm_smem>>>(xh, xl, w1h, w1l, bqkv, qkv, TDIM, DIMM);

    // Attention
    dim3 g2(SEQ / 128, BATCH * HEADS);
    attn_mma<<<g2, 256, attn_smem>>>(causal, att);

    // Split attention output, then out-projection (bf16x3)
    split_kernel<<<BT * DIMM / 4 / 256, 256>>>((const float4*)att, (__nv_bfloat162*)ah, (__nv_bfloat162*)al, BT * DIMM / 4);
    dim3 g3(DIMM / 128, BT / 128);
    bf_gemm<false><<<g3, 256, gemm_smem>>>(ah, al, w2h, w2l, bout, out, DIMM, DIMM);
}

// round 15
// speedup vs baseline: 1.2714x; 1.2714x over previous
#include <cuda_runtime.h>
#include <math.h>
#include <stdint.h>

#define HEADS 16
#define HD    64
#define SEQ   2048
#define BATCH 2
#define DIMM  1024
#define TDIM  3072
#define BT    (BATCH*SEQ)

// Scratch (no cudaMalloc allowed)
__device__ float g_qkv[(size_t)BT * TDIM];     // tf32-rounded qkv
__device__ float g_att[(size_t)BT * DIMM];     // tf32-rounded attention output
__device__ float g_w1[(size_t)TDIM * DIMM];    // rounded Wqkv
__device__ float g_w2[(size_t)DIMM * DIMM];    // rounded Wout

__device__ __forceinline__ float to_tf32(float x) {
    uint32_t u;
    asm("cvt.rna.tf32.f32 %0, %1;" : "=r"(u) : "f"(x));
    return __uint_as_float(u);
}
__device__ __forceinline__ float ex2(float x) {
    float y;
    asm("ex2.approx.ftz.f32 %0, %1;" : "=f"(y) : "f"(x));
    return y;
}
__device__ __forceinline__ void mma_tf32(float* c, const uint32_t* a, const uint32_t* b) {
    asm volatile(
        "mma.sync.aligned.m16n8k8.row.col.f32.tf32.tf32.f32 "
        "{%0,%1,%2,%3}, {%4,%5,%6,%7}, {%8,%9}, {%0,%1,%2,%3};\n"
        : "+f"(c[0]), "+f"(c[1]), "+f"(c[2]), "+f"(c[3])
        : "r"(a[0]), "r"(a[1]), "r"(a[2]), "r"(a[3]), "r"(b[0]), "r"(b[1]));
}
__device__ __forceinline__ void cp16(uint32_t s, const void* g) {
    asm volatile("cp.async.cg.shared.global [%0], [%1], 16;" :: "r"(s), "l"(g));
}
#define CP_COMMIT() asm volatile("cp.async.commit_group;")
#define CP_WAIT1()  asm volatile("cp.async.wait_group 1;")

// ---------------------------------------------------------------------------
// Prepass: tf32-round weights.
// ---------------------------------------------------------------------------
__global__ void roundw_kernel(const float4* __restrict__ src, float4* __restrict__ dst, int n4)
{
    int i = blockIdx.x * 256 + threadIdx.x;
    if (i < n4) {
        float4 v = src[i];
        v.x = to_tf32(v.x); v.y = to_tf32(v.y); v.z = to_tf32(v.z); v.w = to_tf32(v.w);
        dst[i] = v;
    }
}

// ---------------------------------------------------------------------------
// tf32 GEMM, BK=32, 2-stage cp.async, fragment double-buffering.
// BM=BN=128, 256 threads, warp tile 32x64. Rows 36 floats (144B):
// 16B-aligned for cp.async; frag bank = 4g+t(+8ks) -> conflict-free.
// smem: As[2][128][36] @0, Ws[2][128][36] @36864B; total 73728 B.
// ---------------------------------------------------------------------------
template<bool CVT_A, bool ROUND_OUT>
__global__ __launch_bounds__(256, 2) void tgemm32(
    const float* __restrict__ A, const float* __restrict__ W,
    const float* __restrict__ bias, float* __restrict__ C,
    int N, int K)
{
    extern __shared__ float sm[];
    float* As = sm;                    // [2][128][36]
    float* Ws = sm + 2 * 128 * 36;

    const int tid  = threadIdx.x;
    const int warp = tid >> 5;
    const int lane = tid & 31;
    const int g    = lane >> 2;
    const int t    = lane & 3;
    const int m0 = blockIdx.y * 128;
    const int n0 = blockIdx.x * 128;
    const int wm = (warp >> 1) * 32;
    const int wn = (warp & 1) * 64;

    const uint32_t sa = (uint32_t)__cvta_generic_to_shared(As);
    const uint32_t sw = (uint32_t)__cvta_generic_to_shared(Ws);
    const uint32_t stg = 128 * 36 * 4;  // 18432 B per stage

    auto load_chunk = [&](int it, int s) {
        const int kk = it * 32;
#pragma unroll
        for (int j = 0; j < 4; j++) {
            const int li = tid + j * 256;          // 0..1023
            const int r  = li >> 3;                // row 0..127
            const int cb = (li & 7) * 16;          // byte col offset (4 floats)
            const int c  = (li & 7) * 4;           // float col
            cp16(sa + s * stg + (uint32_t)(r * 144 + cb), A + (size_t)(m0 + r) * K + kk + c);
            cp16(sw + s * stg + (uint32_t)(r * 144 + cb), W + (size_t)(n0 + r) * K + kk + c);
        }
        CP_COMMIT();
    };

    float acc[2][8][4];
#pragma unroll
    for (int mi = 0; mi < 2; mi++)
#pragma unroll
        for (int ni = 0; ni < 8; ni++)
#pragma unroll
            for (int r = 0; r < 4; r++) acc[mi][ni][r] = 0.f;

    load_chunk(0, 0);
    load_chunk(1, 1);

    const int niter = K / 32;
    for (int it = 0; it < niter; it++) {
        const int s = it & 1;
        CP_WAIT1();
        __syncthreads();

        const float* Ab = As + s * 4608;
        const float* Wb = Ws + s * 4608;

        auto loadf = [&](int ks, uint32_t (&af)[2][4], uint32_t (&bf)[8][2]) {
            const int ko = ks * 8;
#pragma unroll
            for (int mi = 0; mi < 2; mi++) {
                const int r = wm + mi * 16;
                float a0 = Ab[(r + g    ) * 36 + ko + t    ];
                float a1 = Ab[(r + g + 8) * 36 + ko + t    ];
                float a2 = Ab[(r + g    ) * 36 + ko + t + 4];
                float a3 = Ab[(r + g + 8) * 36 + ko + t + 4];
                if (CVT_A) { a0 = to_tf32(a0); a1 = to_tf32(a1); a2 = to_tf32(a2); a3 = to_tf32(a3); }
                af[mi][0] = __float_as_uint(a0); af[mi][1] = __float_as_uint(a1);
                af[mi][2] = __float_as_uint(a2); af[mi][3] = __float_as_uint(a3);
            }
#pragma unroll
            for (int ni = 0; ni < 8; ni++) {
                const int c = wn + ni * 8;
                bf[ni][0] = __float_as_uint(Wb[(c + g) * 36 + ko + t    ]);
                bf[ni][1] = __float_as_uint(Wb[(c + g) * 36 + ko + t + 4]);
            }
        };

        uint32_t afr[2][2][4], bfr[2][8][2];
        loadf(0, afr[0], bfr[0]);
#pragma unroll
        for (int ks = 0; ks < 4; ks++) {
            if (ks < 3) loadf(ks + 1, afr[(ks + 1) & 1], bfr[(ks + 1) & 1]);
            const int p = ks & 1;
#pragma unroll
            for (int mi = 0; mi < 2; mi++)
#pragma unroll
                for (int ni = 0; ni < 8; ni++)
                    mma_tf32(acc[mi][ni], afr[p][mi], bfr[p][ni]);
        }
        __syncthreads();

        if (it + 2 < niter) load_chunk(it + 2, s);
        else CP_COMMIT();
    }

#pragma unroll
    for (int mi = 0; mi < 2; mi++) {
#pragma unroll
        for (int ni = 0; ni < 8; ni++) {
            const int n = n0 + wn + ni * 8 + 2 * t;
            const float b0 = bias[n], b1 = bias[n + 1];
            const int mA = m0 + wm + mi * 16 + g;
            float2 v0, v1;
            if (ROUND_OUT) {
                v0.x = to_tf32(acc[mi][ni][0] + b0); v0.y = to_tf32(acc[mi][ni][1] + b1);
                v1.x = to_tf32(acc[mi][ni][2] + b0); v1.y = to_tf32(acc[mi][ni][3] + b1);
            } else {
                v0.x = acc[mi][ni][0] + b0; v0.y = acc[mi][ni][1] + b1;
                v1.x = acc[mi][ni][2] + b0; v1.y = acc[mi][ni][3] + b1;
            }
            *(float2*)&C[(size_t)mA * N + n] = v0;
            *(float2*)&C[(size_t)(mA + 8) * N + n] = v1;
        }
    }
}

// ---------------------------------------------------------------------------
// Flash attention (R13 structure), tf32 mma, cp.async double-buffered K/V,
// warp-private smem P tile for the PV permute. Epilogue rounds to tf32 so
// the out-projection GEMM runs cvt-free.
// smem floats: stage0 [0,8704), stage1 [8704,17408), P/Qstage [17408,26112).
// ---------------------------------------------------------------------------
__global__ __launch_bounds__(256, 1) void attn_mma(const int* __restrict__ causal_p,
                                                   float* __restrict__ out)
{
    extern __shared__ float sm[];
    float* Ps = sm + 2 * 8704;

    const int qtile = (int)(gridDim.x - 1 - blockIdx.x);   // heavy tiles first
    const int bh    = blockIdx.y;
    const int b     = bh >> 4;
    const int h     = bh & 15;
    const int tid   = threadIdx.x;
    const int w     = tid >> 5;
    const int lane  = tid & 31;
    const int g     = lane >> 2;
    const int t     = lane & 3;
    const int causal = *causal_p;

    const float sscale = 0.125f * 1.4426950408889634f;
    const float slope2 = (float)(exp2(-0.5 * (double)(h + 1)) * 1.4426950408889634);

    const float* qkv = g_qkv;
    const int q0 = qtile * 128;
    const int rg  = q0 + w * 16 + g;
    const int rg8 = rg + 8;

    const uint32_t smu = (uint32_t)__cvta_generic_to_shared(sm);

    // KV tile 0 -> stage 0
#pragma unroll
    for (int itr = 0; itr < 4; itr++) {
        const int i = itr * 256 + tid;
        const int row = i >> 4;
        const int c4  = (i & 15) * 4;
        const float* gk = qkv + (size_t)(b * SEQ + row) * TDIM + h * HD + DIMM + c4;
        const uint32_t dk = smu + (uint32_t)(row * 68 + c4) * 4;
        cp16(dk, gk);
        cp16(dk + 4352 * 4, gk + DIMM);
    }
    CP_COMMIT();

    // Q -> P region (staging), fragment to registers
    for (int itr = 0; itr < 8; itr++) {
        const int i = itr * 256 + tid;
        const int row = i >> 4;
        const int c4  = (i & 15) * 4;
        *(float4*)&Ps[row * 68 + c4] =
            *(const float4*)&qkv[(size_t)(b * SEQ + q0 + row) * TDIM + h * HD + c4];
    }
    __syncthreads();

    uint32_t qa[8][4];
#pragma unroll
    for (int k = 0; k < 8; k++) {
        qa[k][0] = __float_as_uint(Ps[(w * 16 + g    ) * 68 + k * 8 + t    ]);
        qa[k][1] = __float_as_uint(Ps[(w * 16 + g + 8) * 68 + k * 8 + t    ]);
        qa[k][2] = __float_as_uint(Ps[(w * 16 + g    ) * 68 + k * 8 + t + 4]);
        qa[k][3] = __float_as_uint(Ps[(w * 16 + g + 8) * 68 + k * 8 + t + 4]);
    }
    __syncthreads();

    const int ntiles = causal ? (2 * qtile + 2) : (SEQ / 64);

    // KV tile 1 -> stage 1
    if (ntiles > 1) {
#pragma unroll
        for (int itr = 0; itr < 4; itr++) {
            const int i = itr * 256 + tid;
            const int row = i >> 4;
            const int c4  = (i & 15) * 4;
            const float* gk = qkv + (size_t)(b * SEQ + 64 + row) * TDIM + h * HD + DIMM + c4;
            const uint32_t dk = smu + (uint32_t)(8704 + row * 68 + c4) * 4;
            cp16(dk, gk);
            cp16(dk + 4352 * 4, gk + DIMM);
        }
    }
    CP_COMMIT();

    float o[8][4];
#pragma unroll
    for (int ni = 0; ni < 8; ni++)
#pragma unroll
        for (int r = 0; r < 4; r++) o[ni][r] = 0.f;
    float m0 = -1e30f, m1 = -1e30f, l0 = 0.f, l1 = 0.f;

    float* Pw0 = Ps + (w * 16 + g) * 68;
    float* Pw1 = Pw0 + 8 * 68;

    for (int kt = 0; kt < ntiles; kt++) {
        CP_WAIT1();
        __syncthreads();

        const float* Ks = sm + (kt & 1) * 8704;
        const float* Vs = Ks + 4352;

        const bool active = !(causal && kt * 64 > q0 + w * 16 + 15);
        if (active) {
            // ---- S = Q K^T ----
            float sc[8][4];
#pragma unroll
            for (int ni = 0; ni < 8; ni++)
#pragma unroll
                for (int r = 0; r < 4; r++) sc[ni][r] = 0.f;

#pragma unroll
            for (int k = 0; k < 8; k++) {
                uint32_t kb[8][2];
#pragma unroll
                for (int ni = 0; ni < 8; ni++) {
                    kb[ni][0] = __float_as_uint(Ks[(ni * 8 + g) * 68 + k * 8 + t    ]);
                    kb[ni][1] = __float_as_uint(Ks[(ni * 8 + g) * 68 + k * 8 + t + 4]);
                }
#pragma unroll
                for (int ni = 0; ni < 8; ni++)
                    mma_tf32(sc[ni], qa[k], kb[ni]);
            }

            // ---- Online softmax (log2 domain, ALiBi analytic) ----
            float mx0 = -1e30f, mx1 = -1e30f;
#pragma unroll
            for (int ni = 0; ni < 8; ni++) {
#pragma unroll
                for (int e = 0; e < 2; e++) {
                    const int col = kt * 64 + ni * 8 + 2 * t + e;
                    float v0 = fmaf(sc[ni][e],     sscale, slope2 * (float)(col - rg));
                    float v1 = fmaf(sc[ni][2 + e], sscale, slope2 * (float)(col - rg8));
                    if (causal && col > rg)  v0 = -1e30f;
                    if (causal && col > rg8) v1 = -1e30f;
                    sc[ni][e]     = v0;
                    sc[ni][2 + e] = v1;
                    mx0 = fmaxf(mx0, v0);
                    mx1 = fmaxf(mx1, v1);
                }
            }
            mx0 = fmaxf(mx0, __shfl_xor_sync(0xffffffffu, mx0, 1));
            mx0 = fmaxf(mx0, __shfl_xor_sync(0xffffffffu, mx0, 2));
            mx1 = fmaxf(mx1, __shfl_xor_sync(0xffffffffu, mx1, 1));
            mx1 = fmaxf(mx1, __shfl_xor_sync(0xffffffffu, mx1, 2));

            const float mn0 = fmaxf(m0, mx0);
            const float mn1 = fmaxf(m1, mx1);
            const float rs0 = ex2(m0 - mn0);
            const float rs1 = ex2(m1 - mn1);

            float sum0 = 0.f, sum1 = 0.f;
#pragma unroll
            for (int ni = 0; ni < 8; ni++) {
                float p00 = ex2(sc[ni][0] - mn0);
                float p01 = ex2(sc[ni][1] - mn0);
                float p10 = ex2(sc[ni][2] - mn1);
                float p11 = ex2(sc[ni][3] - mn1);
                sum0 += p00 + p01;
                sum1 += p10 + p11;
                float2 w0v; w0v.x = p00; w0v.y = p01;
                float2 w1v; w1v.x = p10; w1v.y = p11;
                *(float2*)&Pw0[ni * 8 + 2 * t] = w0v;
                *(float2*)&Pw1[ni * 8 + 2 * t] = w1v;
            }
            sum0 += __shfl_xor_sync(0xffffffffu, sum0, 1);
            sum0 += __shfl_xor_sync(0xffffffffu, sum0, 2);
            sum1 += __shfl_xor_sync(0xffffffffu, sum1, 1);
            sum1 += __shfl_xor_sync(0xffffffffu, sum1, 2);

            l0 = l0 * rs0 + sum0;
            l1 = l1 * rs1 + sum1;
            m0 = mn0; m1 = mn1;
#pragma unroll
            for (int ni = 0; ni < 8; ni++) {
                o[ni][0] *= rs0; o[ni][1] *= rs0;
                o[ni][2] *= rs1; o[ni][3] *= rs1;
            }
            __syncwarp();

            // ---- O += P V ----
#pragma unroll
            for (int kc = 0; kc < 8; kc++) {
                uint32_t pa[4];
                pa[0] = __float_as_uint(Pw0[kc * 8 + t    ]);
                pa[1] = __float_as_uint(Pw1[kc * 8 + t    ]);
                pa[2] = __float_as_uint(Pw0[kc * 8 + t + 4]);
                pa[3] = __float_as_uint(Pw1[kc * 8 + t + 4]);

                uint32_t vb[8][2];
#pragma unroll
                for (int ni = 0; ni < 8; ni++) {
                    vb[ni][0] = __float_as_uint(Vs[(kc * 8 + t    ) * 68 + ni * 8 + g]);
                    vb[ni][1] = __float_as_uint(Vs[(kc * 8 + t + 4) * 68 + ni * 8 + g]);
                }
#pragma unroll
                for (int ni = 0; ni < 8; ni++)
                    mma_tf32(o[ni], pa, vb[ni]);
            }
            __syncwarp();
        }
        __syncthreads();

        // Prefetch tile kt+2 into stage (kt&1)
        if (kt + 2 < ntiles) {
#pragma unroll
            for (int itr = 0; itr < 4; itr++) {
                const int i = itr * 256 + tid;
                const int row = i >> 4;
                const int c4  = (i & 15) * 4;
                const float* gk = qkv + (size_t)(b * SEQ + (kt + 2) * 64 + row) * TDIM + h * HD + DIMM + c4;
                const uint32_t dk = smu + (uint32_t)((kt & 1) * 8704 + row * 68 + c4) * 4;
                cp16(dk, gk);
                cp16(dk + 4352 * 4, gk + DIMM);
            }
        }
        CP_COMMIT();
    }

    // ---- Epilogue (tf32-rounded for cvt-free out-projection) ----
    const float inv0 = 1.f / l0;
    const float inv1 = 1.f / l1;
    const size_t row0 = (size_t)(b * SEQ + rg ) * DIMM + h * HD;
    const size_t row1 = (size_t)(b * SEQ + rg8) * DIMM + h * HD;
#pragma unroll
    for (int ni = 0; ni < 8; ni++) {
        const int n = ni * 8 + 2 * t;
        float2 v0; v0.x = to_tf32(o[ni][0] * inv0); v0.y = to_tf32(o[ni][1] * inv0);
        *(float2*)&out[row0 + n] = v0;
        float2 v1; v1.x = to_tf32(o[ni][2] * inv1); v1.y = to_tf32(o[ni][3] * inv1);
        *(float2*)&out[row1 + n] = v1;
    }
}

extern "C" void kernel_launch(void* const* d_in, const int* in_sizes, int n_in,
                              void* d_out, int out_size)
{
    const float* x      = (const float*)d_in[0];
    const int*   causal = (const int*)d_in[1];
    // d_in[2] = alibi_bias: unused (computed analytically in-kernel)
    const float* Wqkv   = (const float*)d_in[3];
    const float* bqkv   = (const float*)d_in[4];
    const float* Wout   = (const float*)d_in[5];
    const float* bout   = (const float*)d_in[6];
    float* out = (float*)d_out;

    float *qkv, *att, *w1, *w2;
    cudaGetSymbolAddress((void**)&qkv, g_qkv);
    cudaGetSymbolAddress((void**)&att, g_att);
    cudaGetSymbolAddress((void**)&w1, g_w1);
    cudaGetSymbolAddress((void**)&w2, g_w2);

    const int gemm_smem = 2 * 2 * 128 * 36 * 4;   // 73728 B
    const int attn_smem = 3 * 8704 * 4;           // 104448 B
    static bool attr_set = false;
    if (!attr_set) {
        cudaFuncSetAttribute(tgemm32<true, true>,   cudaFuncAttributeMaxDynamicSharedMemorySize, gemm_smem);
        cudaFuncSetAttribute(tgemm32<false, false>, cudaFuncAttributeMaxDynamicSharedMemorySize, gemm_smem);
        cudaFuncSetAttribute(attn_mma, cudaFuncAttributeMaxDynamicSharedMemorySize, attn_smem);
        attr_set = true;
    }

    // Prepass: round weights
    roundw_kernel<<<(TDIM * DIMM / 4 + 255) / 256, 256>>>((const float4*)Wqkv, (float4*)w1, TDIM * DIMM / 4);
    roundw_kernel<<<(DIMM * DIMM / 4 + 255) / 256, 256>>>((const float4*)Wout, (float4*)w2, DIMM * DIMM / 4);

    dim3 g1(TDIM / 128, BT / 128);
    tgemm32<true, true><<<g1, 256, gemm_smem>>>(x, w1, bqkv, qkv, TDIM, DIMM);

    dim3 g2(SEQ / 128, BATCH * HEADS);
    attn_mma<<<g2, 256, attn_smem>>>(causal, att);

    dim3 g3(DIMM / 128, BT / 128);
    tgemm32<false, false><<<g3, 256, gemm_smem>>>(att, w2, bout, out, DIMM, DIMM);
}